// round 6
// baseline (speedup 1.0000x reference)
#include <cuda_runtime.h>
#include <math.h>

#define BB   128
#define NN   8192
#define MM   64
#define HID  512
#define OUTC 256
#define REPR 70
#define SEQW 63
#define NCHUNK 16
#define PGRID  888          // 148 SMs * 6 blocks

// ---------------- scratch (device globals) ----------------
__device__ float g_kr[BB*MM];
__device__ float g_kw[BB*MM];
__device__ float g_par[BB*16];
__device__ float g_ae[BB*MM];
__device__ float g_aux[BB*4];               // 0:||ae||^2  1:ae.kr  2:S=sum(ww*wr)
__device__ float g_msum_part[NCHUNK*BB*MM];
__device__ float g_out_part [NCHUNK*BB*MM];
__device__ float g_dkw[BB*NN];
__device__ float g_dkr[BB*NN];
__device__ float g_n2 [BB*NN];
__device__ float g_dae[BB*NN];
__device__ float g_ww [BB*NN];
__device__ float g_wr [BB*NN];
__device__ float g_tmp [BB*NN];
__device__ float g_tmp2[BB*NN];
__device__ unsigned g_cntA[BB];             // zero-init; reset by tails each launch
__device__ unsigned g_cntC[BB];

__device__ __forceinline__ float lrelu(float v){ return (v>0.f)? v : 0.01f*v; }

// ---- block reductions ----
__device__ __forceinline__ float bredsum(float v, float* sred, int nw){
    const int lane = threadIdx.x & 31, wid = threadIdx.x >> 5;
    #pragma unroll
    for (int o=16;o>0;o>>=1) v += __shfl_xor_sync(0xffffffffu, v, o);
    if (lane==0) sred[wid]=v;
    __syncthreads();
    if (wid==0){
        float w = (lane<nw)? sred[lane] : 0.f;
        #pragma unroll
        for (int o=16;o>0;o>>=1) w += __shfl_xor_sync(0xffffffffu, w, o);
        if (lane==0) sred[0]=w;
    }
    __syncthreads();
    float r = sred[0];
    __syncthreads();
    return r;
}
__device__ __forceinline__ float bredmax(float v, float* sred, int nw){
    const int lane = threadIdx.x & 31, wid = threadIdx.x >> 5;
    #pragma unroll
    for (int o=16;o>0;o>>=1) v = fmaxf(v, __shfl_xor_sync(0xffffffffu, v, o));
    if (lane==0) sred[wid]=v;
    __syncthreads();
    if (wid==0){
        float w = (lane<nw)? sred[lane] : -1e30f;
        #pragma unroll
        for (int o=16;o>0;o>>=1) w = fmaxf(w, __shfl_xor_sync(0xffffffffu, w, o));
        if (lane==0) sred[0]=w;
    }
    __syncthreads();
    float r = sred[0];
    __syncthreads();
    return r;
}

// ---------------- fused controller ----------------
__global__ void __launch_bounds__(256) k_ctrl(
    const float* __restrict__ x,
    const float* __restrict__ W0, const float* __restrict__ b0,
    const float* __restrict__ W1, const float* __restrict__ b1,
    const float* __restrict__ Wc, const float* __restrict__ bc,
    const float* __restrict__ Wr, const float* __restrict__ br,
    const float* __restrict__ Ww, const float* __restrict__ bw,
    const float* __restrict__ wrp, const float* __restrict__ wwp)
{
    const int b = blockIdx.x;
    const int t = threadIdx.x;
    __shared__ float xs[SEQW+1];
    __shared__ float h0s[HID];
    __shared__ float h1s[HID];
    __shared__ float cs_[OUTC];
    __shared__ float rr[REPR];
    __shared__ float rw[REPR];
    __shared__ float sred[32];

    if (t < SEQW+1) xs[t] = x[b*(SEQW+1)+t];
    __syncthreads();

    {
        float a0 = b0[t], a1 = b0[t+256];
        #pragma unroll
        for (int i=0;i<SEQW+1;i++){
            float v = xs[i];
            a0 = fmaf(v, W0[i*HID + t],     a0);
            a1 = fmaf(v, W0[i*HID + t+256], a1);
        }
        h0s[t] = lrelu(a0); h0s[t+256] = lrelu(a1);
    }
    __syncthreads();
    {
        float a0 = b1[t], a1 = b1[t+256];
        #pragma unroll 8
        for (int i=0;i<HID;i++){
            float v = h0s[i];
            a0 = fmaf(v, W1[i*HID + t],     a0);
            a1 = fmaf(v, W1[i*HID + t+256], a1);
        }
        h1s[t] = lrelu(a0); h1s[t+256] = lrelu(a1);
    }
    __syncthreads();
    {
        float a0 = bc[t];
        #pragma unroll 8
        for (int i=0;i<HID;i++)
            a0 = fmaf(h1s[i], Wc[i*OUTC + t], a0);
        cs_[t] = lrelu(a0);
    }
    __syncthreads();
    if (t < REPR){
        float a = br[t];
        #pragma unroll 8
        for (int i=0;i<OUTC;i++) a = fmaf(cs_[i], Wr[i*REPR + t], a);
        rr[t] = a;
    } else if (t >= 128 && t < 128+REPR){
        const int j = t-128;
        float a = bw[j];
        #pragma unroll 8
        for (int i=0;i<OUTC;i++) a = fmaf(cs_[i], Ww[i*REPR + j], a);
        rw[j] = a;
    }
    __syncthreads();

    float vr = 0.f, vw = 0.f;
    if (t < MM){
        vr = rr[t]; vw = rw[t];
        g_kr[b*MM+t] = vr; g_kw[b*MM+t] = vw;
    }
    float nr = bredsum(vr*vr, sred, 8);
    float nw_ = bredsum(vw*vw, sred, 8);
    if (t==0){ g_par[b*16+12]=sqrtf(nr); g_par[b*16+13]=sqrtf(nw_); }

    const size_t base = (size_t)b*NN;
    float sr=0.f, sw=0.f;
    for (int n=t; n<NN; n+=256){ sr += wrp[base+n]; sw += wwp[base+n]; }
    sr = bredsum(sr, sred, 8);
    sw = bredsum(sw, sred, 8);
    if (t==0){ g_par[b*16+14]=1.f/sr; g_par[b*16+15]=1.f/sw; }

    if (t==0){
        float* p = &g_par[b*16];
        p[0] = fmaxf(rr[64],0.f)+1e-8f;
        p[1] = 1.f/(1.f+__expf(-rr[65]));
        {
            float m = fmaxf(rr[66], fmaxf(rr[67], rr[68]));
            float e0=__expf(rr[66]-m), e1=__expf(rr[67]-m), e2=__expf(rr[68]-m);
            float s=e0+e1+e2;
            p[2]=e0/s; p[3]=e1/s; p[4]=e2/s;
        }
        p[5] = fmaxf(rr[69],0.f)+1.f;
        p[6] = fmaxf(rw[64],0.f)+1e-8f;
        p[7] = 1.f/(1.f+__expf(-rw[65]));
        {
            float m = fmaxf(rw[66], fmaxf(rw[67], rw[68]));
            float e0=__expf(rw[66]-m), e1=__expf(rw[67]-m), e2=__expf(rw[68]-m);
            float s=e0+e1+e2;
            p[8]=e0/s; p[9]=e1/s; p[10]=e2/s;
        }
        p[11] = fmaxf(rw[69],0.f)+1.f;
    }
}

// ---------------- ea tail (run by last-finishing passA block for batch b, 256 thr) ----------------
__device__ void ea_tail(int b, const float* __restrict__ Wea, const float* __restrict__ bea)
{
    __shared__ float ma[MM], kws[MM], eas[2*MM], sred2[32];
    const int t = threadIdx.x;
    if (t<MM){
        float s = 0.f;
        #pragma unroll
        for (int c=0;c<NCHUNK;c++) s += g_msum_part[(c*BB + b)*MM + t];
        ma[t]  = s * (1.f/(float)NN);
        kws[t] = g_kw[b*MM+t];
    }
    __syncthreads();
    if (t < 2*MM){
        float acc = bea[t];
        #pragma unroll 8
        for (int i=0;i<MM;i++)  acc = fmaf(ma[i],  Wea[i*(2*MM)+t],      acc);
        #pragma unroll 8
        for (int i=0;i<MM;i++)  acc = fmaf(kws[i], Wea[(MM+i)*(2*MM)+t], acc);
        eas[t]=acc;
    }
    __syncthreads();
    float ae=0.f, krv=0.f;
    if (t<MM){
        float e = 1.f/(1.f+__expf(-eas[t]));
        ae = eas[MM+t]-e;
        g_ae[b*MM+t]=ae;
        krv = g_kr[b*MM+t];
    }
    float a2 = bredsum(ae*ae, sred2, 8);
    float ak = bredsum(ae*krv, sred2, 8);
    if (t==0){ g_aux[b*4+0]=a2; g_aux[b*4+1]=ak; }
}

// ---------------- pass A: persistent grid + ea tail ----------------
__global__ void __launch_bounds__(256) k_passA(const float* __restrict__ bank,
                                               const float* __restrict__ Wea,
                                               const float* __restrict__ bea)
{
    __shared__ float scs[MM];
    __shared__ int flag;
    const int warp = threadIdx.x >> 5;
    const int lane = threadIdx.x & 31;
    const int half = lane >> 4;
    const int sub  = lane & 15;

    for (int u = blockIdx.x; u < BB*NCHUNK; u += PGRID){
        const int b = u >> 4, chunk = u & 15;
        const size_t bbase = (size_t)b * NN;
        const float4 kw4 = *reinterpret_cast<const float4*>(&g_kw[b*MM + sub*4]);
        const float4 kr4 = *reinterpret_cast<const float4*>(&g_kr[b*MM + sub*4]);

        float4 cs = make_float4(0.f,0.f,0.f,0.f);
        const int row0 = chunk*512 + warp*64;
        for (int it=0; it<8; it++){
            float4 v[4]; int row[4];
            #pragma unroll
            for (int j=0;j<4;j++){
                row[j] = row0 + it*8 + j*2 + half;
                v[j] = *reinterpret_cast<const float4*>(bank + (bbase + row[j])*MM + sub*4);
            }
            float dkw[4], dkr[4], nn[4];
            #pragma unroll
            for (int j=0;j<4;j++){
                dkw[j] = v[j].x*kw4.x + v[j].y*kw4.y + v[j].z*kw4.z + v[j].w*kw4.w;
                dkr[j] = v[j].x*kr4.x + v[j].y*kr4.y + v[j].z*kr4.z + v[j].w*kr4.w;
                nn [j] = v[j].x*v[j].x + v[j].y*v[j].y + v[j].z*v[j].z + v[j].w*v[j].w;
                cs.x += v[j].x; cs.y += v[j].y; cs.z += v[j].z; cs.w += v[j].w;
            }
            #pragma unroll
            for (int off=8; off>0; off>>=1){
                #pragma unroll
                for (int j=0;j<4;j++){
                    dkw[j] += __shfl_xor_sync(0xffffffffu, dkw[j], off);
                    dkr[j] += __shfl_xor_sync(0xffffffffu, dkr[j], off);
                    nn [j] += __shfl_xor_sync(0xffffffffu, nn [j], off);
                }
            }
            if (sub == 0){
                #pragma unroll
                for (int j=0;j<4;j++){
                    g_dkw[bbase+row[j]] = dkw[j];
                    g_dkr[bbase+row[j]] = dkr[j];
                    g_n2 [bbase+row[j]] = nn [j];
                }
            }
        }
        cs.x += __shfl_xor_sync(0xffffffffu, cs.x, 16);
        cs.y += __shfl_xor_sync(0xffffffffu, cs.y, 16);
        cs.z += __shfl_xor_sync(0xffffffffu, cs.z, 16);
        cs.w += __shfl_xor_sync(0xffffffffu, cs.w, 16);

        if (threadIdx.x < MM) scs[threadIdx.x] = 0.f;
        __syncthreads();
        if (half == 0){
            atomicAdd(&scs[sub*4+0], cs.x);
            atomicAdd(&scs[sub*4+1], cs.y);
            atomicAdd(&scs[sub*4+2], cs.z);
            atomicAdd(&scs[sub*4+3], cs.w);
        }
        __syncthreads();
        if (threadIdx.x < MM)
            g_msum_part[(chunk*BB + b)*MM + threadIdx.x] = scs[threadIdx.x];

        __threadfence();
        __syncthreads();
        if (threadIdx.x == 0){
            unsigned c = atomicAdd(&g_cntA[b], 1u);
            flag = (c == NCHUNK-1);
            if (flag) g_cntA[b] = 0u;          // reset for next graph replay
        }
        __syncthreads();
        if (flag) ea_tail(b, Wea, bea);
        __syncthreads();
    }
}

// ---------------- write addressing (global scratch) ----------------
__device__ void addr_write_global(int b, const float* __restrict__ wprev)
{
    __shared__ float sred[32];
    const int t = threadIdx.x;      // 256
    const size_t base = (size_t)b*NN;
    float* arr  = &g_tmp [base];
    float* arr2 = &g_tmp2[base];
    const float* p = &g_par[b*16];
    const float beta=p[6], gg=p[7], s0=p[8], s1=p[9], s2=p[10], gamma=p[11];
    const float nk=p[13], invs=p[15];

    float lmax = -1e30f;
    for (int i=0;i<32;i++){
        int n = t + i*256;
        float cosv = __fdividef(g_dkw[base+n], fmaxf(sqrtf(g_n2[base+n])*nk, 1e-8f));
        float tv = beta*cosv;
        arr[n]=tv;
        lmax = fmaxf(lmax, tv);
    }
    const float bmax = bredmax(lmax, sred, 8);

    float lsum=0.f;
    for (int i=0;i<32;i++){
        int n=t+i*256;
        float e = __expf(arr[n]-bmax);
        arr[n]=e; lsum+=e;
    }
    const float invsum = __fdividef(1.f, bredsum(lsum, sred, 8));

    for (int i=0;i<32;i++){
        int n=t+i*256;
        float wc  = arr[n]*invsum;
        arr[n] = gg*wc + (1.f-gg)*wprev[base+n]*invs;
    }
    __syncthreads();

    float lps=0.f;
    for (int i=0;i<32;i++){
        int n=t+i*256;
        float ws = s0*arr[(n+NN-1)&(NN-1)] + s1*arr[n] + s2*arr[(n+1)&(NN-1)];
        float wp = __powf(ws, gamma);
        arr2[n]=wp; lps+=wp;
    }
    const float invp = __fdividef(1.f, bredsum(lps, sred, 8));

    for (int i=0;i<32;i++){
        int n=t+i*256;
        g_ww[base+n] = arr2[n]*invp;
    }
}

// ---------------- fused: addrW blocks FIRST (0..127), then persistent passB ----------------
__global__ void __launch_bounds__(256) k_fusedB(const float* __restrict__ bank,
                                                const float* __restrict__ wwp)
{
    if (blockIdx.x < BB){
        addr_write_global(blockIdx.x, wwp);
        return;
    }
    const int warp = threadIdx.x >> 5;
    const int lane = threadIdx.x & 31;
    const int half = lane >> 4;
    const int sub  = lane & 15;
    for (int u = blockIdx.x - BB; u < BB*NCHUNK; u += PGRID){
        const int b = u >> 4, chunk = u & 15;
        const size_t bbase = (size_t)b * NN;
        const float4 ae4 = *reinterpret_cast<const float4*>(&g_ae[b*MM + sub*4]);
        const int row0 = chunk*512 + warp*64;
        for (int it=0; it<8; it++){
            float4 v[4]; int row[4];
            #pragma unroll
            for (int j=0;j<4;j++){
                row[j] = row0 + it*8 + j*2 + half;
                v[j] = *reinterpret_cast<const float4*>(bank + (bbase + row[j])*MM + sub*4);
            }
            float d[4];
            #pragma unroll
            for (int j=0;j<4;j++)
                d[j] = v[j].x*ae4.x + v[j].y*ae4.y + v[j].z*ae4.z + v[j].w*ae4.w;
            #pragma unroll
            for (int off=8; off>0; off>>=1)
                #pragma unroll
                for (int j=0;j<4;j++)
                    d[j] += __shfl_xor_sync(0xffffffffu, d[j], off);
            if (sub == 0){
                #pragma unroll
                for (int j=0;j<4;j++) g_dae[bbase+row[j]] = d[j];
            }
        }
    }
}

// ---------------- read addressing (1024 threads) ----------------
__global__ void __launch_bounds__(1024) k_addrR(const float* __restrict__ wrp)
{
    __shared__ float arr[NN];
    __shared__ float sred[32];
    const int b = blockIdx.x;
    const int t = threadIdx.x;
    const size_t base = (size_t)b*NN;
    const float* p = &g_par[b*16];
    const float beta=p[0], gg=p[1], s0=p[2], s1=p[3], s2=p[4], gamma=p[5];
    const float nk=p[12], invs=p[14];
    const float ae2=g_aux[b*4], aekr=g_aux[b*4+1];

    float lmax = -1e30f;
    #pragma unroll
    for (int i=0;i<8;i++){
        int n = t + i*1024;
        float w  = g_ww[base+n];
        float d  = g_dkr[base+n] + w*aekr;
        float nn = fmaxf(g_n2[base+n] + 2.f*w*g_dae[base+n] + w*w*ae2, 0.f);
        float cosv = __fdividef(d, fmaxf(sqrtf(nn)*nk, 1e-8f));
        float tv = beta*cosv;
        arr[n]=tv;
        lmax = fmaxf(lmax, tv);
    }
    const float bmax = bredmax(lmax, sred, 32);

    float lsum=0.f;
    #pragma unroll
    for (int i=0;i<8;i++){
        int n=t+i*1024;
        float e = __expf(arr[n]-bmax);
        arr[n]=e; lsum+=e;
    }
    const float invsum = __fdividef(1.f, bredsum(lsum, sred, 32));

    #pragma unroll
    for (int i=0;i<8;i++){
        int n=t+i*1024;
        float wc  = arr[n]*invsum;
        arr[n] = gg*wc + (1.f-gg)*wrp[base+n]*invs;
    }
    __syncthreads();

    float wp_loc[8];
    float lps=0.f;
    #pragma unroll
    for (int i=0;i<8;i++){
        int n=t+i*1024;
        float ws = s0*arr[(n+NN-1)&(NN-1)] + s1*arr[n] + s2*arr[(n+1)&(NN-1)];
        float wp = __powf(ws, gamma);
        wp_loc[i]=wp; lps+=wp;
    }
    const float invp = __fdividef(1.f, bredsum(lps, sred, 32));

    float lS=0.f;
    #pragma unroll
    for (int i=0;i<8;i++){
        int n=t+i*1024;
        float w = wp_loc[i]*invp;
        g_wr[base+n]=w;
        lS += g_ww[base+n]*w;
    }
    float S = bredsum(lS, sred, 32);
    if (t==0) g_aux[b*4+2]=S;
}

// ---------------- final head tail (run by last passC block for batch b, 256 thr) ----------------
__device__ void final_tail(int b,
                           const float* __restrict__ Wsp, const float* __restrict__ bsp,
                           const float* __restrict__ Wo,  const float* __restrict__ bo,
                           float* __restrict__ out)
{
    __shared__ float om[MM], seq[HID];
    const int t = threadIdx.x;
    if (t<MM){
        float s = 0.f;
        #pragma unroll
        for (int c=0;c<NCHUNK;c++) s += g_out_part[(c*BB + b)*MM + t];
        om[t] = s + g_aux[b*4+2]*g_ae[b*MM+t];
    }
    __syncthreads();
    for (int j=t; j<HID; j+=256){
        float a = bsp[j];
        #pragma unroll 8
        for (int i=0;i<MM;i++) a = fmaf(om[i], Wsp[i*HID+j], a);
        seq[j] = lrelu(a);
    }
    __syncthreads();
    if (t<SEQW){
        float a = bo[t];
        for (int i=0;i<HID;i++) a = fmaf(seq[i], Wo[i*SEQW+t], a);
        out[b*SEQW+t] = 1.f/(1.f+__expf(-a));
    }
}

// ---------------- pass C: persistent grid + final tail ----------------
__global__ void __launch_bounds__(256) k_passC(const float* __restrict__ bank,
                                               const float* __restrict__ Wsp,
                                               const float* __restrict__ bsp,
                                               const float* __restrict__ Wo,
                                               const float* __restrict__ bo,
                                               float* __restrict__ out)
{
    __shared__ float scs[MM];
    __shared__ int flag;
    const int warp = threadIdx.x >> 5;
    const int lane = threadIdx.x & 31;
    const int half = lane >> 4;
    const int sub  = lane & 15;

    for (int u = blockIdx.x; u < BB*NCHUNK; u += PGRID){
        const int b = u >> 4, chunk = u & 15;
        const size_t bbase = (size_t)b * NN;

        float4 acc = make_float4(0.f,0.f,0.f,0.f);
        const int row0 = chunk*512 + warp*64;
        for (int it=0; it<8; it++){
            float4 v[4]; float wr[4];
            #pragma unroll
            for (int j=0;j<4;j++){
                int row = row0 + it*8 + j*2 + half;
                wr[j] = g_wr[bbase+row];
                v[j] = *reinterpret_cast<const float4*>(bank + (bbase + row)*MM + sub*4);
            }
            #pragma unroll
            for (int j=0;j<4;j++){
                acc.x = fmaf(v[j].x, wr[j], acc.x);
                acc.y = fmaf(v[j].y, wr[j], acc.y);
                acc.z = fmaf(v[j].z, wr[j], acc.z);
                acc.w = fmaf(v[j].w, wr[j], acc.w);
            }
        }
        acc.x += __shfl_xor_sync(0xffffffffu, acc.x, 16);
        acc.y += __shfl_xor_sync(0xffffffffu, acc.y, 16);
        acc.z += __shfl_xor_sync(0xffffffffu, acc.z, 16);
        acc.w += __shfl_xor_sync(0xffffffffu, acc.w, 16);

        if (threadIdx.x < MM) scs[threadIdx.x] = 0.f;
        __syncthreads();
        if (half == 0){
            atomicAdd(&scs[sub*4+0], acc.x);
            atomicAdd(&scs[sub*4+1], acc.y);
            atomicAdd(&scs[sub*4+2], acc.z);
            atomicAdd(&scs[sub*4+3], acc.w);
        }
        __syncthreads();
        if (threadIdx.x < MM)
            g_out_part[(chunk*BB + b)*MM + threadIdx.x] = scs[threadIdx.x];

        __threadfence();
        __syncthreads();
        if (threadIdx.x == 0){
            unsigned c = atomicAdd(&g_cntC[b], 1u);
            flag = (c == NCHUNK-1);
            if (flag) g_cntC[b] = 0u;
        }
        __syncthreads();
        if (flag) final_tail(b, Wsp, bsp, Wo, bo, out);
        __syncthreads();
    }
}

// ---------------- launch ----------------
extern "C" void kernel_launch(void* const* d_in, const int* in_sizes, int n_in,
                              void* d_out, int out_size)
{
    const float* x    = (const float*)d_in[0];
    const float* bank = (const float*)d_in[1];
    const float* wrp  = (const float*)d_in[2];
    const float* wwp  = (const float*)d_in[3];
    const float* W0   = (const float*)d_in[4];
    const float* b0   = (const float*)d_in[5];
    const float* W1   = (const float*)d_in[6];
    const float* b1   = (const float*)d_in[7];
    const float* Wc   = (const float*)d_in[8];
    const float* bc   = (const float*)d_in[9];
    const float* Wr   = (const float*)d_in[10];
    const float* br   = (const float*)d_in[11];
    const float* Ww   = (const float*)d_in[12];
    const float* bw   = (const float*)d_in[13];
    const float* Wea  = (const float*)d_in[14];
    const float* bea  = (const float*)d_in[15];
    const float* Wsp  = (const float*)d_in[16];
    const float* bsp  = (const float*)d_in[17];
    const float* Wo   = (const float*)d_in[18];
    const float* bo   = (const float*)d_in[19];
    float* out = (float*)d_out;

    k_ctrl<<<BB, 256>>>(x, W0,b0, W1,b1, Wc,bc, Wr,br, Ww,bw, wrp, wwp);
    k_passA<<<PGRID, 256>>>(bank, Wea, bea);              // persistent + ea tails
    k_fusedB<<<BB + PGRID, 256>>>(bank, wwp);             // addrW first, then persistent passB
    k_addrR<<<BB, 1024>>>(wrp);
    k_passC<<<PGRID, 256>>>(bank, Wsp, bsp, Wo, bo, out); // persistent + final tails
}

// round 7
// speedup vs baseline: 1.1360x; 1.1360x over previous
#include <cuda_runtime.h>
#include <math.h>

#define BB   128
#define NN   8192
#define MM   64
#define HID  512
#define OUTC 256
#define REPR 70
#define SEQW 63
#define NCHUNK 64           // 128 rows per chunk

// ---------------- scratch (device globals) ----------------
__device__ float g_kr[BB*MM];
__device__ float g_kw[BB*MM];
__device__ float g_par[BB*16];
__device__ float g_ae[BB*MM];
__device__ float g_aux[BB*4];               // 0:||ae||^2  1:ae.kr  2:S=sum(ww*wr)
__device__ float g_msum_part[NCHUNK*BB*MM]; // 2 MB
__device__ float g_out_part [NCHUNK*BB*MM]; // 2 MB
__device__ float g_dkw[BB*NN];
__device__ float g_dkr[BB*NN];
__device__ float g_n2 [BB*NN];
__device__ float g_dae[BB*NN];
__device__ float g_ww [BB*NN];
__device__ float g_wr [BB*NN];
__device__ float g_tmp [BB*NN];
__device__ float g_tmp2[BB*NN];

__device__ __forceinline__ float lrelu(float v){ return (v>0.f)? v : 0.01f*v; }

// ---- block reductions ----
__device__ __forceinline__ float bredsum(float v, float* sred, int nw){
    const int lane = threadIdx.x & 31, wid = threadIdx.x >> 5;
    #pragma unroll
    for (int o=16;o>0;o>>=1) v += __shfl_xor_sync(0xffffffffu, v, o);
    if (lane==0) sred[wid]=v;
    __syncthreads();
    if (wid==0){
        float w = (lane<nw)? sred[lane] : 0.f;
        #pragma unroll
        for (int o=16;o>0;o>>=1) w += __shfl_xor_sync(0xffffffffu, w, o);
        if (lane==0) sred[0]=w;
    }
    __syncthreads();
    float r = sred[0];
    __syncthreads();
    return r;
}
__device__ __forceinline__ float bredmax(float v, float* sred, int nw){
    const int lane = threadIdx.x & 31, wid = threadIdx.x >> 5;
    #pragma unroll
    for (int o=16;o>0;o>>=1) v = fmaxf(v, __shfl_xor_sync(0xffffffffu, v, o));
    if (lane==0) sred[wid]=v;
    __syncthreads();
    if (wid==0){
        float w = (lane<nw)? sred[lane] : -1e30f;
        #pragma unroll
        for (int o=16;o>0;o>>=1) w = fmaxf(w, __shfl_xor_sync(0xffffffffu, w, o));
        if (lane==0) sred[0]=w;
    }
    __syncthreads();
    float r = sred[0];
    __syncthreads();
    return r;
}

// ---------------- fused controller ----------------
__global__ void __launch_bounds__(256) k_ctrl(
    const float* __restrict__ x,
    const float* __restrict__ W0, const float* __restrict__ b0,
    const float* __restrict__ W1, const float* __restrict__ b1,
    const float* __restrict__ Wc, const float* __restrict__ bc,
    const float* __restrict__ Wr, const float* __restrict__ br,
    const float* __restrict__ Ww, const float* __restrict__ bw,
    const float* __restrict__ wrp, const float* __restrict__ wwp)
{
    const int b = blockIdx.x;
    const int t = threadIdx.x;
    __shared__ float xs[SEQW+1];
    __shared__ float h0s[HID];
    __shared__ float h1s[HID];
    __shared__ float cs_[OUTC];
    __shared__ float rr[REPR];
    __shared__ float rw[REPR];
    __shared__ float sred[32];

    if (t < SEQW+1) xs[t] = x[b*(SEQW+1)+t];
    __syncthreads();

    {
        float a0 = b0[t], a1 = b0[t+256];
        #pragma unroll
        for (int i=0;i<SEQW+1;i++){
            float v = xs[i];
            a0 = fmaf(v, W0[i*HID + t],     a0);
            a1 = fmaf(v, W0[i*HID + t+256], a1);
        }
        h0s[t] = lrelu(a0); h0s[t+256] = lrelu(a1);
    }
    __syncthreads();
    {
        float a0 = b1[t], a1 = b1[t+256];
        #pragma unroll 8
        for (int i=0;i<HID;i++){
            float v = h0s[i];
            a0 = fmaf(v, W1[i*HID + t],     a0);
            a1 = fmaf(v, W1[i*HID + t+256], a1);
        }
        h1s[t] = lrelu(a0); h1s[t+256] = lrelu(a1);
    }
    __syncthreads();
    {
        float a0 = bc[t];
        #pragma unroll 8
        for (int i=0;i<HID;i++)
            a0 = fmaf(h1s[i], Wc[i*OUTC + t], a0);
        cs_[t] = lrelu(a0);
    }
    __syncthreads();
    if (t < REPR){
        float a = br[t];
        #pragma unroll 8
        for (int i=0;i<OUTC;i++) a = fmaf(cs_[i], Wr[i*REPR + t], a);
        rr[t] = a;
    } else if (t >= 128 && t < 128+REPR){
        const int j = t-128;
        float a = bw[j];
        #pragma unroll 8
        for (int i=0;i<OUTC;i++) a = fmaf(cs_[i], Ww[i*REPR + j], a);
        rw[j] = a;
    }
    __syncthreads();

    float vr = 0.f, vw = 0.f;
    if (t < MM){
        vr = rr[t]; vw = rw[t];
        g_kr[b*MM+t] = vr; g_kw[b*MM+t] = vw;
    }
    float nr = bredsum(vr*vr, sred, 8);
    float nw_ = bredsum(vw*vw, sred, 8);
    if (t==0){ g_par[b*16+12]=sqrtf(nr); g_par[b*16+13]=sqrtf(nw_); }

    const size_t base = (size_t)b*NN;
    float sr=0.f, sw=0.f;
    for (int n=t; n<NN; n+=256){ sr += wrp[base+n]; sw += wwp[base+n]; }
    sr = bredsum(sr, sred, 8);
    sw = bredsum(sw, sred, 8);
    if (t==0){ g_par[b*16+14]=1.f/sr; g_par[b*16+15]=1.f/sw; }

    if (t==0){
        float* p = &g_par[b*16];
        p[0] = fmaxf(rr[64],0.f)+1e-8f;
        p[1] = 1.f/(1.f+__expf(-rr[65]));
        {
            float m = fmaxf(rr[66], fmaxf(rr[67], rr[68]));
            float e0=__expf(rr[66]-m), e1=__expf(rr[67]-m), e2=__expf(rr[68]-m);
            float s=e0+e1+e2;
            p[2]=e0/s; p[3]=e1/s; p[4]=e2/s;
        }
        p[5] = fmaxf(rr[69],0.f)+1.f;
        p[6] = fmaxf(rw[64],0.f)+1e-8f;
        p[7] = 1.f/(1.f+__expf(-rw[65]));
        {
            float m = fmaxf(rw[66], fmaxf(rw[67], rw[68]));
            float e0=__expf(rw[66]-m), e1=__expf(rw[67]-m), e2=__expf(rw[68]-m);
            float s=e0+e1+e2;
            p[8]=e0/s; p[9]=e1/s; p[10]=e2/s;
        }
        p[11] = fmaxf(rw[69],0.f)+1.f;
    }
}

// ---------------- pass A: dkw, ||row||^2, column sums (NO dkr) ----------------
// grid (64, 128), 256 threads. warp handles 16 rows of its chunk.
__global__ void __launch_bounds__(256) k_passA(const float* __restrict__ bank)
{
    const int b = blockIdx.y;
    const int chunk = blockIdx.x;
    const int warp = threadIdx.x >> 5;
    const int lane = threadIdx.x & 31;
    const int half = lane >> 4;
    const int sub  = lane & 15;
    const size_t bbase = (size_t)b * NN;

    const float4 kw4 = *reinterpret_cast<const float4*>(&g_kw[b*MM + sub*4]);

    float4 cs = make_float4(0.f,0.f,0.f,0.f);
    const int row0 = chunk*128 + warp*16;
    #pragma unroll
    for (int bat=0; bat<2; bat++){
        float4 v[4]; int row[4];
        #pragma unroll
        for (int j=0;j<4;j++){
            row[j] = row0 + bat*8 + j*2 + half;
            v[j] = *reinterpret_cast<const float4*>(bank + (bbase + row[j])*MM + sub*4);
        }
        float dkw[4], nn[4];
        #pragma unroll
        for (int j=0;j<4;j++){
            dkw[j] = v[j].x*kw4.x + v[j].y*kw4.y + v[j].z*kw4.z + v[j].w*kw4.w;
            nn [j] = v[j].x*v[j].x + v[j].y*v[j].y + v[j].z*v[j].z + v[j].w*v[j].w;
            cs.x += v[j].x; cs.y += v[j].y; cs.z += v[j].z; cs.w += v[j].w;
        }
        #pragma unroll
        for (int off=8; off>0; off>>=1){
            #pragma unroll
            for (int j=0;j<4;j++){
                dkw[j] += __shfl_xor_sync(0xffffffffu, dkw[j], off);
                nn [j] += __shfl_xor_sync(0xffffffffu, nn [j], off);
            }
        }
        if (sub == 0){
            #pragma unroll
            for (int j=0;j<4;j++){
                g_dkw[bbase+row[j]] = dkw[j];
                g_n2 [bbase+row[j]] = nn [j];
            }
        }
    }
    cs.x += __shfl_xor_sync(0xffffffffu, cs.x, 16);
    cs.y += __shfl_xor_sync(0xffffffffu, cs.y, 16);
    cs.z += __shfl_xor_sync(0xffffffffu, cs.z, 16);
    cs.w += __shfl_xor_sync(0xffffffffu, cs.w, 16);

    __shared__ float scs[MM];
    if (threadIdx.x < MM) scs[threadIdx.x] = 0.f;
    __syncthreads();
    if (half == 0){
        atomicAdd(&scs[sub*4+0], cs.x);
        atomicAdd(&scs[sub*4+1], cs.y);
        atomicAdd(&scs[sub*4+2], cs.z);
        atomicAdd(&scs[sub*4+3], cs.w);
    }
    __syncthreads();
    if (threadIdx.x < MM)
        g_msum_part[(chunk*BB + b)*MM + threadIdx.x] = scs[threadIdx.x];
}

// ---------------- erase/add vector ----------------
__global__ void k_ea(const float* __restrict__ Wea, const float* __restrict__ bea)
{
    const int b=blockIdx.x, t=threadIdx.x;   // 128 threads
    __shared__ float ma[MM], kws[MM], eas[2*MM], sred[32];
    if (t<MM){
        float s = 0.f;
        #pragma unroll 16
        for (int c=0;c<NCHUNK;c++) s += g_msum_part[(c*BB + b)*MM + t];
        ma[t]  = s * (1.f/(float)NN);
        kws[t] = g_kw[b*MM+t];
    }
    __syncthreads();
    float acc = bea[t];
    #pragma unroll 8
    for (int i=0;i<MM;i++)  acc = fmaf(ma[i],  Wea[i*(2*MM)+t],      acc);
    #pragma unroll 8
    for (int i=0;i<MM;i++)  acc = fmaf(kws[i], Wea[(MM+i)*(2*MM)+t], acc);
    eas[t]=acc;
    __syncthreads();
    float ae=0.f, krv=0.f;
    if (t<MM){
        float e = 1.f/(1.f+__expf(-eas[t]));
        ae = eas[MM+t]-e;
        g_ae[b*MM+t]=ae;
        krv = g_kr[b*MM+t];
    }
    float a2 = bredsum(ae*ae, sred, 4);
    float ak = bredsum(ae*krv, sred, 4);
    if (t==0){ g_aux[b*4+0]=a2; g_aux[b*4+1]=ak; }
}

// ---------------- write addressing (global scratch) ----------------
__device__ void addr_write_global(int b, const float* __restrict__ wprev)
{
    __shared__ float sred[32];
    const int t = threadIdx.x;      // 256
    const size_t base = (size_t)b*NN;
    float* arr  = &g_tmp [base];
    float* arr2 = &g_tmp2[base];
    const float* p = &g_par[b*16];
    const float beta=p[6], gg=p[7], s0=p[8], s1=p[9], s2=p[10], gamma=p[11];
    const float nk=p[13], invs=p[15];

    float lmax = -1e30f;
    for (int i=0;i<32;i++){
        int n = t + i*256;
        float cosv = __fdividef(g_dkw[base+n], fmaxf(sqrtf(g_n2[base+n])*nk, 1e-8f));
        float tv = beta*cosv;
        arr[n]=tv;
        lmax = fmaxf(lmax, tv);
    }
    const float bmax = bredmax(lmax, sred, 8);

    float lsum=0.f;
    for (int i=0;i<32;i++){
        int n=t+i*256;
        float e = __expf(arr[n]-bmax);
        arr[n]=e; lsum+=e;
    }
    const float invsum = __fdividef(1.f, bredsum(lsum, sred, 8));

    for (int i=0;i<32;i++){
        int n=t+i*256;
        float wc  = arr[n]*invsum;
        arr[n] = gg*wc + (1.f-gg)*wprev[base+n]*invs;
    }
    __syncthreads();

    float lps=0.f;
    for (int i=0;i<32;i++){
        int n=t+i*256;
        float ws = s0*arr[(n+NN-1)&(NN-1)] + s1*arr[n] + s2*arr[(n+1)&(NN-1)];
        float wp = __powf(ws, gamma);
        arr2[n]=wp; lps+=wp;
    }
    const float invp = __fdividef(1.f, bredsum(lps, sred, 8));

    for (int i=0;i<32;i++){
        int n=t+i*256;
        g_ww[base+n] = arr2[n]*invp;
    }
}

// ---------------- fused: addrW (blocks 0..127, scheduled FIRST) + passB (dae AND dkr) ----------------
__global__ void __launch_bounds__(256) k_fusedB(const float* __restrict__ bank,
                                                const float* __restrict__ wwp)
{
    if (blockIdx.x < BB){
        addr_write_global(blockIdx.x, wwp);
        return;
    }
    const int u = blockIdx.x - BB;
    const int b = u >> 6, chunk = u & 63;
    const int warp = threadIdx.x >> 5;
    const int lane = threadIdx.x & 31;
    const int half = lane >> 4;
    const int sub  = lane & 15;
    const size_t bbase = (size_t)b * NN;
    const float4 ae4 = *reinterpret_cast<const float4*>(&g_ae[b*MM + sub*4]);
    const float4 kr4 = *reinterpret_cast<const float4*>(&g_kr[b*MM + sub*4]);
    const int row0 = chunk*128 + warp*16;
    #pragma unroll
    for (int bat=0; bat<2; bat++){
        float4 v[4]; int row[4];
        #pragma unroll
        for (int j=0;j<4;j++){
            row[j] = row0 + bat*8 + j*2 + half;
            v[j] = *reinterpret_cast<const float4*>(bank + (bbase + row[j])*MM + sub*4);
        }
        float d[4], dk[4];
        #pragma unroll
        for (int j=0;j<4;j++){
            d [j] = v[j].x*ae4.x + v[j].y*ae4.y + v[j].z*ae4.z + v[j].w*ae4.w;
            dk[j] = v[j].x*kr4.x + v[j].y*kr4.y + v[j].z*kr4.z + v[j].w*kr4.w;
        }
        #pragma unroll
        for (int off=8; off>0; off>>=1){
            #pragma unroll
            for (int j=0;j<4;j++){
                d [j] += __shfl_xor_sync(0xffffffffu, d [j], off);
                dk[j] += __shfl_xor_sync(0xffffffffu, dk[j], off);
            }
        }
        if (sub == 0){
            #pragma unroll
            for (int j=0;j<4;j++){
                g_dae[bbase+row[j]] = d [j];
                g_dkr[bbase+row[j]] = dk[j];
            }
        }
    }
}

// ---------------- read addressing (1024 threads) ----------------
__global__ void __launch_bounds__(1024) k_addrR(const float* __restrict__ wrp)
{
    __shared__ float arr[NN];
    __shared__ float sred[32];
    const int b = blockIdx.x;
    const int t = threadIdx.x;
    const size_t base = (size_t)b*NN;
    const float* p = &g_par[b*16];
    const float beta=p[0], gg=p[1], s0=p[2], s1=p[3], s2=p[4], gamma=p[5];
    const float nk=p[12], invs=p[14];
    const float ae2=g_aux[b*4], aekr=g_aux[b*4+1];

    float lmax = -1e30f;
    #pragma unroll
    for (int i=0;i<8;i++){
        int n = t + i*1024;
        float w  = g_ww[base+n];
        float d  = g_dkr[base+n] + w*aekr;
        float nn = fmaxf(g_n2[base+n] + 2.f*w*g_dae[base+n] + w*w*ae2, 0.f);
        float cosv = __fdividef(d, fmaxf(sqrtf(nn)*nk, 1e-8f));
        float tv = beta*cosv;
        arr[n]=tv;
        lmax = fmaxf(lmax, tv);
    }
    const float bmax = bredmax(lmax, sred, 32);

    float lsum=0.f;
    #pragma unroll
    for (int i=0;i<8;i++){
        int n=t+i*1024;
        float e = __expf(arr[n]-bmax);
        arr[n]=e; lsum+=e;
    }
    const float invsum = __fdividef(1.f, bredsum(lsum, sred, 32));

    #pragma unroll
    for (int i=0;i<8;i++){
        int n=t+i*1024;
        float wc  = arr[n]*invsum;
        arr[n] = gg*wc + (1.f-gg)*wrp[base+n]*invs;
    }
    __syncthreads();

    float wp_loc[8];
    float lps=0.f;
    #pragma unroll
    for (int i=0;i<8;i++){
        int n=t+i*1024;
        float ws = s0*arr[(n+NN-1)&(NN-1)] + s1*arr[n] + s2*arr[(n+1)&(NN-1)];
        float wp = __powf(ws, gamma);
        wp_loc[i]=wp; lps+=wp;
    }
    const float invp = __fdividef(1.f, bredsum(lps, sred, 32));

    float lS=0.f;
    #pragma unroll
    for (int i=0;i<8;i++){
        int n=t+i*1024;
        float w = wp_loc[i]*invp;
        g_wr[base+n]=w;
        lS += g_ww[base+n]*w;
    }
    float S = bredsum(lS, sred, 32);
    if (t==0) g_aux[b*4+2]=S;
}

// ---------------- pass C ----------------
__global__ void __launch_bounds__(256) k_passC(const float* __restrict__ bank)
{
    const int b = blockIdx.y;
    const int chunk = blockIdx.x;
    const int warp = threadIdx.x >> 5;
    const int lane = threadIdx.x & 31;
    const int half = lane >> 4;
    const int sub  = lane & 15;
    const size_t bbase = (size_t)b * NN;

    float4 acc = make_float4(0.f,0.f,0.f,0.f);
    const int row0 = chunk*128 + warp*16;
    #pragma unroll
    for (int bat=0; bat<2; bat++){
        float4 v[4]; float wr[4];
        #pragma unroll
        for (int j=0;j<4;j++){
            int row = row0 + bat*8 + j*2 + half;
            wr[j] = g_wr[bbase+row];
            v[j] = *reinterpret_cast<const float4*>(bank + (bbase + row)*MM + sub*4);
        }
        #pragma unroll
        for (int j=0;j<4;j++){
            acc.x = fmaf(v[j].x, wr[j], acc.x);
            acc.y = fmaf(v[j].y, wr[j], acc.y);
            acc.z = fmaf(v[j].z, wr[j], acc.z);
            acc.w = fmaf(v[j].w, wr[j], acc.w);
        }
    }
    acc.x += __shfl_xor_sync(0xffffffffu, acc.x, 16);
    acc.y += __shfl_xor_sync(0xffffffffu, acc.y, 16);
    acc.z += __shfl_xor_sync(0xffffffffu, acc.z, 16);
    acc.w += __shfl_xor_sync(0xffffffffu, acc.w, 16);

    __shared__ float scs[MM];
    if (threadIdx.x < MM) scs[threadIdx.x] = 0.f;
    __syncthreads();
    if (half == 0){
        atomicAdd(&scs[sub*4+0], acc.x);
        atomicAdd(&scs[sub*4+1], acc.y);
        atomicAdd(&scs[sub*4+2], acc.z);
        atomicAdd(&scs[sub*4+3], acc.w);
    }
    __syncthreads();
    if (threadIdx.x < MM)
        g_out_part[(chunk*BB + b)*MM + threadIdx.x] = scs[threadIdx.x];
}

// ---------------- final head ----------------
__global__ void k_final(const float* __restrict__ Wsp, const float* __restrict__ bsp,
                        const float* __restrict__ Wo,  const float* __restrict__ bo,
                        float* __restrict__ out)
{
    const int b=blockIdx.x, t=threadIdx.x;   // 128
    __shared__ float om[MM], seq[HID];
    if (t<MM){
        float s = 0.f;
        #pragma unroll 16
        for (int c=0;c<NCHUNK;c++) s += g_out_part[(c*BB + b)*MM + t];
        om[t] = s + g_aux[b*4+2]*g_ae[b*MM+t];
    }
    __syncthreads();
    for (int j=t; j<HID; j+=128){
        float a = bsp[j];
        #pragma unroll 8
        for (int i=0;i<MM;i++) a = fmaf(om[i], Wsp[i*HID+j], a);
        seq[j] = lrelu(a);
    }
    __syncthreads();
    if (t<SEQW){
        float a = bo[t];
        for (int i=0;i<HID;i++) a = fmaf(seq[i], Wo[i*SEQW+t], a);
        out[b*SEQW+t] = 1.f/(1.f+__expf(-a));
    }
}

// ---------------- launch ----------------
extern "C" void kernel_launch(void* const* d_in, const int* in_sizes, int n_in,
                              void* d_out, int out_size)
{
    const float* x    = (const float*)d_in[0];
    const float* bank = (const float*)d_in[1];
    const float* wrp  = (const float*)d_in[2];
    const float* wwp  = (const float*)d_in[3];
    const float* W0   = (const float*)d_in[4];
    const float* b0   = (const float*)d_in[5];
    const float* W1   = (const float*)d_in[6];
    const float* b1   = (const float*)d_in[7];
    const float* Wc   = (const float*)d_in[8];
    const float* bc   = (const float*)d_in[9];
    const float* Wr   = (const float*)d_in[10];
    const float* br   = (const float*)d_in[11];
    const float* Ww   = (const float*)d_in[12];
    const float* bw   = (const float*)d_in[13];
    const float* Wea  = (const float*)d_in[14];
    const float* bea  = (const float*)d_in[15];
    const float* Wsp  = (const float*)d_in[16];
    const float* bsp  = (const float*)d_in[17];
    const float* Wo   = (const float*)d_in[18];
    const float* bo   = (const float*)d_in[19];
    float* out = (float*)d_out;

    k_ctrl<<<BB, 256>>>(x, W0,b0, W1,b1, Wc,bc, Wr,br, Ww,bw, wrp, wwp);
    k_passA<<<dim3(NCHUNK, BB), 256>>>(bank);            // dkw + n2 + colsums
    k_ea<<<BB, 128>>>(Wea, bea);
    k_fusedB<<<BB + NCHUNK*BB, 256>>>(bank, wwp);        // addrW first, then passB (dae + dkr)
    k_addrR<<<BB, 1024>>>(wrp);
    k_passC<<<dim3(NCHUNK, BB), 256>>>(bank);
    k_final<<<BB, 128>>>(Wsp, bsp, Wo, bo, out);
}